// round 4
// baseline (speedup 1.0000x reference)
#include <cuda_runtime.h>
#include <stdint.h>

#define N_NODES_MAX 100000
#define E_MAX       1200000
#define NFEAT 64
#define NHID  256
#define NCLASS 40
#define ORDER 8

// ---------------- scratch (device globals; no allocation) ----------------
__device__ __align__(256) float g_h0[N_NODES_MAX * NFEAT];
__device__ __align__(256) float g_h1[N_NODES_MAX * NFEAT];
__device__ __align__(256) float g_y [N_NODES_MAX * NFEAT];
// combined zero-initialized workspace: [0,N)=cnt, [N,2N)=fill, [2N,2N+256)=scan flags
__device__ int   g_ws[2 * N_NODES_MAX + 256];
__device__ float g_dinv[N_NODES_MAX];
__device__ int   g_rowptr[N_NODES_MAX + 1];
__device__ int   g_col[E_MAX];
__device__ float g_w  [E_MAX];
__device__ int   g_is64;

#define CNT(i)  g_ws[i]
#define FILL(i) g_ws[N_NODES_MAX + (i)]
#define FLAG(b) g_ws[2 * N_NODES_MAX + (b)]

// ---------------- packed f32x2 helpers (FFMA2 — PTX-only path) ----------
__device__ __forceinline__ unsigned long long pack2(float lo, float hi) {
    unsigned long long r;
    asm("mov.b64 %0, {%1, %2};" : "=l"(r) : "f"(lo), "f"(hi));
    return r;
}
__device__ __forceinline__ void fma2(unsigned long long& d,
                                     unsigned long long a,
                                     unsigned long long b) {
    asm("fma.rn.f32x2 %0, %1, %2, %0;" : "+l"(d) : "l"(a), "l"(b));
}
__device__ __forceinline__ float2 unpack2(unsigned long long v) {
    float2 r;
    asm("mov.b64 {%0, %1}, %2;" : "=f"(r.x), "=f"(r.y) : "l"(v));
    return r;
}

// ---------------- edge-index dtype detection ----------------
// Reference asks int64 but JAX without x64 silently yields int32. Node ids
// < 1e5, so int32 data read as int64 gives values >= 2^32 unless the paired
// high id is exactly 0 (~1e-5 per sample; 64 samples -> robust).
__global__ void k_detect(const void* ei) {
    if (threadIdx.x == 0 && blockIdx.x == 0) {
        const unsigned long long* p = (const unsigned long long*)ei;
        int is64 = 1;
        for (int i = 0; i < 64; i++) {
            if (p[i] >= (unsigned long long)N_NODES_MAX) { is64 = 0; break; }
        }
        g_is64 = is64;
    }
}

__device__ __forceinline__ int edge_at(const void* ei, int idx) {
    if (g_is64) return (int)((const long long*)ei)[idx];
    return ((const int*)ei)[idx];
}

// ---------------- preprocessing ----------------
__global__ void k_hist(const void* __restrict__ ei, int E) {
    int e = blockIdx.x * blockDim.x + threadIdx.x;
    if (e < E) atomicAdd(&CNT(edge_at(ei, e)), 1);
}

// Fused: dinv + exclusive-scan of degree counts -> rowptr.
// StreamScan: block b spins on FLAG(b-1). Grid = ceil(n/1024) = 98 blocks,
// all resident simultaneously on 148 SMs -> no deadlock, deterministic output.
__global__ __launch_bounds__(1024) void k_scan(int n, int E, int ntiles) {
    __shared__ int s[1024];
    __shared__ int s_prefix;
    int tid = threadIdx.x;
    int b   = blockIdx.x;
    int i   = b * 1024 + tid;
    int c   = (i < n) ? CNT(i) : 0;
    if (i < n) g_dinv[i] = rsqrtf((float)(c + 1));  // +1 self-loop
    s[tid] = c;
    __syncthreads();
    #pragma unroll
    for (int off = 1; off < 1024; off <<= 1) {
        int t = (tid >= off) ? s[tid - off] : 0;
        __syncthreads();
        s[tid] += t;
        __syncthreads();
    }
    if (tid == 1023) {
        int prefix = 0;
        if (b > 0) {
            int v = atomicAdd(&FLAG(b - 1), 0);
            while (v == 0) {                 // backoff poll: don't hammer the
                __nanosleep(64);             // single LTS atomic slot shared by
                v = atomicAdd(&FLAG(b - 1), 0);  // all waiting blocks
            }
            prefix = v - 1;
        }
        atomicExch(&FLAG(b), prefix + s[1023] + 1);
        s_prefix = prefix;
    }
    __syncthreads();
    if (i < n) g_rowptr[i] = s_prefix + s[tid] - c;  // exclusive
    if (b == 0 && tid == 0) g_rowptr[n] = E;
}

// Fused: CSR scatter (blocks [0,Eb)) + h0/y init (blocks [Eb, Eb+Nb)).
__global__ void k_scatter_init(const void* __restrict__ ei, int E,
                               const float4* __restrict__ x, int n4, int Eb) {
    if ((int)blockIdx.x < Eb) {
        int e = blockIdx.x * blockDim.x + threadIdx.x;
        if (e >= E) return;
        int r = edge_at(ei, e);
        int c = edge_at(ei, E + e);
        int pos = g_rowptr[r] + atomicAdd(&FILL(r), 1);
        g_col[pos] = c;
        g_w[pos] = g_dinv[r] * g_dinv[c];
    } else {
        int i = ((int)blockIdx.x - Eb) * blockDim.x + threadIdx.x;
        if (i < n4) {
            float4 v = x[i];
            v.x *= 0.5f; v.y *= 0.5f; v.z *= 0.5f; v.w *= 0.5f;
            ((float4*)g_h0)[i] = v;
            ((float4*)g_y)[i]  = v;
        }
    }
}

// ---------------- SPMM: warp-per-row CSR gather, fused y accumulation -----
// Uniform LDGs for col/w (single-sector broadcast). 4 independent
// accumulator pairs keep 4 h[col] gathers in flight per warp; the tail is a
// predicated 4-wide group (w=0 padding -> exact), never a serial MLP=1 loop.
__global__ __launch_bounds__(256) void k_spmm(const float* __restrict__ hsrc,
                                              float* __restrict__ hdst, int n) {
    int w = (blockIdx.x * blockDim.x + threadIdx.x) >> 5;
    int lane = threadIdx.x & 31;
    if (w >= n) return;
    const float2* __restrict__ hs = (const float2*)hsrc;
    float dv = g_dinv[w];
    float2 hv = hs[w * 32 + lane];
    float sw = dv * dv;            // self-loop weight
    float ax0 = sw * hv.x, ay0 = sw * hv.y;
    float ax1 = 0.f, ay1 = 0.f, ax2 = 0.f, ay2 = 0.f, ax3 = 0.f, ay3 = 0.f;
    int beg = g_rowptr[w], end = g_rowptr[w + 1];
    for (int j = beg; j < end; j += 4) {
        // predicated 4-wide group: out-of-range slots read a valid address
        // (the last edge) with weight 0 -> contributes exactly nothing.
        bool p1 = (j + 1 < end), p2 = (j + 2 < end), p3 = (j + 3 < end);
        int   c0 = __ldg(&g_col[j]);
        int   c1 = __ldg(&g_col[p1 ? j + 1 : j]);
        int   c2 = __ldg(&g_col[p2 ? j + 2 : j]);
        int   c3 = __ldg(&g_col[p3 ? j + 3 : j]);
        float w0 = __ldg(&g_w[j]);
        float w1 = p1 ? __ldg(&g_w[j + 1]) : 0.f;
        float w2 = p2 ? __ldg(&g_w[j + 2]) : 0.f;
        float w3 = p3 ? __ldg(&g_w[j + 3]) : 0.f;
        float2 v0 = hs[c0 * 32 + lane];
        float2 v1 = hs[c1 * 32 + lane];
        float2 v2 = hs[c2 * 32 + lane];
        float2 v3 = hs[c3 * 32 + lane];
        ax0 = fmaf(w0, v0.x, ax0);  ay0 = fmaf(w0, v0.y, ay0);
        ax1 = fmaf(w1, v1.x, ax1);  ay1 = fmaf(w1, v1.y, ay1);
        ax2 = fmaf(w2, v2.x, ax2);  ay2 = fmaf(w2, v2.y, ay2);
        ax3 = fmaf(w3, v3.x, ax3);  ay3 = fmaf(w3, v3.y, ay3);
    }
    float ax = (ax0 + ax1) + (ax2 + ax3);
    float ay = (ay0 + ay1) + (ay2 + ay3);
    float2 a; a.x = ax; a.y = ay;
    ((float2*)hdst)[w * 32 + lane] = a;
    float2* yp = (float2*)g_y;
    float2 yy = yp[w * 32 + lane];
    yy.x += ax; yy.y += ay;
    yp[w * 32 + lane] = yy;
}

// ---------------- fused MLP: relu(y/9 @ W1 + b1) @ W2 + b2 ----------------
// 32 rows per block; all inner products via packed fma.rn.f32x2 (FFMA2).
#define HID_STRIDE 257  // pad to dodge bank conflicts in GEMM2 reads
#define SMEM_FLOATS (64*256 + 256*40 + 32*64 + 32*HID_STRIDE + 4*32*40)

__global__ __launch_bounds__(256) void k_mlp(const float* __restrict__ y,
                                             const float* __restrict__ W1,
                                             const float* __restrict__ b1,
                                             const float* __restrict__ W2,
                                             const float* __restrict__ b2,
                                             float* __restrict__ out, int n) {
    extern __shared__ float sm[];
    float* W1s = sm;                    // [64][256]
    float* W2s = W1s + 64 * 256;        // [256][40]
    float* ys  = W2s + 256 * 40;        // [32][64]
    float* hid = ys + 32 * 64;          // [32][HID_STRIDE]
    float* red = hid + 32 * HID_STRIDE; // [4][32][40] split-k partials

    int tid = threadIdx.x;
    int row0 = blockIdx.x * 32;
    const float inv9 = 1.0f / 9.0f;

    for (int i = tid; i < 64 * 256; i += 256) W1s[i] = W1[i];
    for (int i = tid; i < 256 * 40; i += 256) W2s[i] = W2[i];
    for (int i = tid; i < 32 * 64; i += 256) {
        int r = i >> 6, g = row0 + r;
        ys[i] = (g < n) ? y[g * 64 + (i & 63)] * inv9 : 0.f;
    }
    __syncthreads();

    // GEMM1: warp w -> rows 4w..4w+3; lane -> cols lane*8..+7 (4 f32x2 pairs)
    int lane = tid & 31, warp = tid >> 5;
    int r0 = warp * 4;
    int c0 = lane * 8;
    unsigned long long acc2[4][4];
    #pragma unroll
    for (int r = 0; r < 4; r++)
        #pragma unroll
        for (int c = 0; c < 4; c++) acc2[r][c] = 0ULL;

    #pragma unroll 4
    for (int k = 0; k < 64; k++) {
        const unsigned long long* wp =
            (const unsigned long long*)&W1s[k * 256 + c0];
        unsigned long long w01 = wp[0], w23 = wp[1], w45 = wp[2], w67 = wp[3];
        #pragma unroll
        for (int r = 0; r < 4; r++) {
            float yv = ys[(r0 + r) * 64 + k];
            unsigned long long y2 = pack2(yv, yv);
            fma2(acc2[r][0], y2, w01);
            fma2(acc2[r][1], y2, w23);
            fma2(acc2[r][2], y2, w45);
            fma2(acc2[r][3], y2, w67);
        }
    }
    #pragma unroll
    for (int c = 0; c < 4; c++) {
        float b_lo = b1[c0 + 2 * c];
        float b_hi = b1[c0 + 2 * c + 1];
        #pragma unroll
        for (int r = 0; r < 4; r++) {
            float2 v = unpack2(acc2[r][c]);
            hid[(r0 + r) * HID_STRIDE + c0 + 2 * c]     = fmaxf(v.x + b_lo, 0.f);
            hid[(r0 + r) * HID_STRIDE + c0 + 2 * c + 1] = fmaxf(v.y + b_hi, 0.f);
        }
    }
    __syncthreads();

    // GEMM2, split-k by 4: group g2 covers k in [g2*64, g2*64+64).
    // Within a 64-thread group: 4 col-groups x 10 cols (5 f32x2), 16 row-groups x 2 rows.
    int g2 = tid >> 6;       // 0..3
    int u  = tid & 63;
    int cg = u & 3;          // cols cg*10 .. +9
    int rg = u >> 2;         // rows rg*2 .. +1
    unsigned long long a2[2][5];
    #pragma unroll
    for (int r = 0; r < 2; r++)
        #pragma unroll
        for (int j = 0; j < 5; j++) a2[r][j] = 0ULL;

    #pragma unroll 4
    for (int kk = 0; kk < 64; kk++) {
        int k = g2 * 64 + kk;
        const unsigned long long* wp =
            (const unsigned long long*)&W2s[k * 40 + cg * 10];
        unsigned long long wv[5];
        #pragma unroll
        for (int j = 0; j < 5; j++) wv[j] = wp[j];
        #pragma unroll
        for (int r = 0; r < 2; r++) {
            float hv = hid[(rg * 2 + r) * HID_STRIDE + k];
            unsigned long long h2 = pack2(hv, hv);
            #pragma unroll
            for (int j = 0; j < 5; j++) fma2(a2[r][j], h2, wv[j]);
        }
    }
    #pragma unroll
    for (int r = 0; r < 2; r++)
        #pragma unroll
        for (int j = 0; j < 5; j++) {
            float2 v = unpack2(a2[r][j]);
            int base = g2 * 1280 + (rg * 2 + r) * 40 + cg * 10 + 2 * j;
            red[base]     = v.x;
            red[base + 1] = v.y;
        }
    __syncthreads();

    for (int i = tid; i < 1280; i += 256) {
        int r = i / 40, c = i % 40;
        float s = red[i] + red[1280 + i] + red[2560 + i] + red[3840 + i] + b2[c];
        int g = row0 + r;
        if (g < n) out[g * 40 + c] = s;
    }
}

// ---------------- launch ----------------
// Launch order is deliberate: k_spmm is the 6th launch so the harness's
// ncu capture (-s 5 -c 1) profiles the dominant kernel next round.
extern "C" void kernel_launch(void* const* d_in, const int* in_sizes, int n_in,
                              void* d_out, int out_size) {
    const float* x  = (const float*)d_in[0];
    const void*  ei = d_in[1];
    const float* W1 = (const float*)d_in[2];
    const float* b1 = (const float*)d_in[3];
    const float* W2 = (const float*)d_in[4];
    const float* b2 = (const float*)d_in[5];
    float* out = (float*)d_out;

    int n = in_sizes[0] / NFEAT;   // 100000
    int E = in_sizes[1] / 2;       // 1200000

    void *wsp, *h0p, *h1p, *yp;
    cudaGetSymbolAddress(&wsp, g_ws);
    cudaGetSymbolAddress(&h0p, g_h0);
    cudaGetSymbolAddress(&h1p, g_h1);
    cudaGetSymbolAddress(&yp,  g_y);

    cudaMemsetAsync(wsp, 0, (2 * N_NODES_MAX + 256) * sizeof(int), 0);  // #1

    k_detect<<<1, 32>>>(ei);                                            // #2
    k_hist<<<(E + 255) / 256, 256>>>(ei, E);                            // #3
    int ntiles = (n + 1023) / 1024;   // 98 (< 148 SMs -> StreamScan safe)
    k_scan<<<ntiles, 1024>>>(n, E, ntiles);                             // #4

    int n4 = n * NFEAT / 4;
    int Eb = (E + 255) / 256;
    int Nb = (n4 + 255) / 256;
    k_scatter_init<<<Eb + Nb, 256>>>(ei, E, (const float4*)x, n4, Eb);  // #5

    float* hA = (float*)h0p;
    float* hB = (float*)h1p;
    int spmmBlocks = (n * 32 + 255) / 256;
    for (int it = 0; it < ORDER; it++) {                                // #6..13
        k_spmm<<<spmmBlocks, 256>>>(hA, hB, n);
        float* t = hA; hA = hB; hB = t;
    }

    size_t smemBytes = (size_t)SMEM_FLOATS * sizeof(float);  // ~168 KB
    cudaFuncSetAttribute(k_mlp, cudaFuncAttributeMaxDynamicSharedMemorySize,
                         (int)smemBytes);
    k_mlp<<<(n + 31) / 32, 256, smemBytes>>>((const float*)yp, W1, b1, W2, b2,
                                             out, n);
}